// round 7
// baseline (speedup 1.0000x reference)
#include <cuda_runtime.h>

// ---------------------------------------------------------------------------
// RModel_29257317221019: fused cos-MLP deform (3->32->32->32->3) + trilinear
// sample from 256^3 volume.
// 4 points per thread:
//   - acc[4][16] f32x2 accumulators in registers (~128 regs)
//   - activations h[32] per point live in SMEM scratch (feature-major,
//     [point][k][lane] -> conflict-free LDS.32/STS.32)
//   - one broadcast LDS.128 of raw weights feeds 8 FFMA2 (2 d-pairs x 4 pts)
//   - dynamic smem 75KB (weights 9.5KB + h-scratch 64KB), 2 CTAs/SM
// ---------------------------------------------------------------------------

typedef unsigned long long u64;

__device__ __forceinline__ void upk2(u64 v, float& lo, float& hi) {
    asm("mov.b64 {%0, %1}, %2;" : "=f"(lo), "=f"(hi) : "l"(v));
}
__device__ __forceinline__ u64 dup2(float v) {
    u64 r; asm("mov.b64 %0, {%1, %1};" : "=l"(r) : "f"(v)); return r;
}
__device__ __forceinline__ u64 ffma2(u64 a, u64 b, u64 c) {
    u64 r; asm("fma.rn.f32x2 %0, %1, %2, %3;" : "=l"(r) : "l"(a), "l"(b), "l"(c)); return r;
}
__device__ __forceinline__ void lds_v2b64(unsigned addr, u64& a, u64& b) {
    asm("ld.shared.v2.b64 {%0, %1}, [%2];" : "=l"(a), "=l"(b) : "r"(addr));
}
__device__ __forceinline__ u64 lds_b64(unsigned addr) {
    u64 a; asm("ld.shared.b64 %0, [%1];" : "=l"(a) : "r"(addr)); return a;
}
__device__ __forceinline__ float lds_f32(unsigned addr) {
    float f; asm("ld.shared.b32 %0, [%1];" : "=f"(f) : "r"(addr)); return f;
}
__device__ __forceinline__ void sts_f32(unsigned addr, float v) {
    asm("st.shared.b32 [%0], %1;" :: "r"(addr), "f"(v));
}

// Shared float layout (weights; all bases 16B aligned)
#define OFF_W1   0      // [3][32]  = 96   (c*32+d)
#define OFF_B1   96     // 32
#define OFF_W2   128    // [32][32] = 1024 (k*32+d)
#define OFF_B2   1152   // 32
#define OFF_W3   1184   // [32][32] = 1024
#define OFF_B3   2208   // 32
#define OFF_WF4  2240   // [32][4]  = 128  (k*4+j, j=3 zero pad)
#define OFF_BF   2368   // 4 (padded)
#define W_TOTAL  2372
// h scratch: [4 warps][4 points][32 features][32 lanes] floats
#define H_OFF    2372
#define BLK      128
#define NP       4
#define SMEM_FLOATS (W_TOTAL + (BLK/32) * NP * 32 * 32)
#define SMEM_BYTES  (SMEM_FLOATS * 4)     // 9488 + 65536 = 75024

// One dense 32->32 layer with cos: reads h from smem scratch, accumulates in
// registers for 4 points sharing every weight load, writes cos(h) back.
__device__ __forceinline__ void dense_cos_layer(
    unsigned sbase, int woff, int boff, const unsigned hb0, const unsigned hb1,
    const unsigned hb2, const unsigned hb3)
{
    u64 acc[NP][16];
#pragma unroll
    for (int j = 0; j < 16; j++) {
        u64 b = lds_b64(sbase + (boff + 2 * j) * 4);
        acc[0][j] = b; acc[1][j] = b; acc[2][j] = b; acc[3][j] = b;
    }
#pragma unroll 8
    for (int k = 0; k < 32; k++) {
        u64 w[16];
        unsigned row = sbase + (woff + k * 32) * 4;
#pragma unroll
        for (int m = 0; m < 8; m++) lds_v2b64(row + 16 * m, w[2 * m], w[2 * m + 1]);
        u64 h0 = dup2(lds_f32(hb0 + k * 128));
        u64 h1 = dup2(lds_f32(hb1 + k * 128));
        u64 h2 = dup2(lds_f32(hb2 + k * 128));
        u64 h3 = dup2(lds_f32(hb3 + k * 128));
#pragma unroll
        for (int j = 0; j < 16; j++) {
            acc[0][j] = ffma2(h0, w[j], acc[0][j]);
            acc[1][j] = ffma2(h1, w[j], acc[1][j]);
            acc[2][j] = ffma2(h2, w[j], acc[2][j]);
            acc[3][j] = ffma2(h3, w[j], acc[3][j]);
        }
    }
    unsigned hb[NP] = { hb0, hb1, hb2, hb3 };
#pragma unroll
    for (int p = 0; p < NP; p++) {
#pragma unroll
        for (int j = 0; j < 16; j++) {
            float lo, hi; upk2(acc[p][j], lo, hi);
            sts_f32(hb[p] + (2 * j + 0) * 128, __cosf(lo));
            sts_f32(hb[p] + (2 * j + 1) * 128, __cosf(hi));
        }
    }
}

__global__ __launch_bounds__(BLK, 2)
void deform_sample_kernel(
    const float* __restrict__ x,
    const float* __restrict__ W1, const float* __restrict__ b1,
    const float* __restrict__ W2, const float* __restrict__ b2,
    const float* __restrict__ W3, const float* __restrict__ b3,
    const float* __restrict__ Wf, const float* __restrict__ bf,
    const float* __restrict__ vol,
    float* __restrict__ out,
    int nthreads)
{
    extern __shared__ __align__(16) float ws[];

    // Cooperative fill of raw weights
    {
        int tid = threadIdx.x;
        for (int i = tid; i < 96;   i += BLK) ws[OFF_W1 + i] = W1[i];
        for (int i = tid; i < 32;   i += BLK) ws[OFF_B1 + i] = b1[i];
        for (int i = tid; i < 1024; i += BLK) ws[OFF_W2 + i] = W2[i];
        for (int i = tid; i < 32;   i += BLK) ws[OFF_B2 + i] = b2[i];
        for (int i = tid; i < 1024; i += BLK) ws[OFF_W3 + i] = W3[i];
        for (int i = tid; i < 32;   i += BLK) ws[OFF_B3 + i] = b3[i];
        for (int i = tid; i < 128;  i += BLK) {
            int k = i >> 2, j = i & 3;
            ws[OFF_WF4 + i] = (j < 3) ? Wf[k * 3 + j] : 0.0f;
        }
        for (int i = tid; i < 4;    i += BLK) ws[OFF_BF + i] = (i < 3) ? bf[i] : 0.0f;
    }
    __syncthreads();

    unsigned sbase = (unsigned)__cvta_generic_to_shared((void*)ws);

    int t = blockIdx.x * blockDim.x + threadIdx.x;
    if (t >= nthreads) return;

    int warp = threadIdx.x >> 5;
    int lane = threadIdx.x & 31;
    // h scratch base per point: feature k lives at hb[p] + k*128 bytes
    unsigned hb0 = sbase + (H_OFF + ((warp * NP + 0) * 32) * 32 + lane) * 4;
    unsigned hb1 = hb0 + 32 * 32 * 4;
    unsigned hb2 = hb1 + 32 * 32 * 4;
    unsigned hb3 = hb2 + 32 * 32 * 4;

    // Load 4 points' coords (x layout: 4 floats/point, coords in [0:3])
    const float4* x4 = reinterpret_cast<const float4*>(x);
    float4 X0 = x4[4 * t + 0];
    float4 X1 = x4[4 * t + 1];
    float4 X2 = x4[4 * t + 2];
    float4 X3 = x4[4 * t + 3];
    float cxr[NP][3] = {
        {X0.x, X0.y, X0.z}, {X1.x, X1.y, X1.z},
        {X2.x, X2.y, X2.z}, {X3.x, X3.y, X3.z} };

    // ---- Layer 1: h = cos(c @ W1 + b1) ----
    {
        u64 cd[NP][3];
#pragma unroll
        for (int p = 0; p < NP; p++) {
            cd[p][0] = dup2(cxr[p][0]);
            cd[p][1] = dup2(cxr[p][1]);
            cd[p][2] = dup2(cxr[p][2]);
        }
        unsigned hb[NP] = { hb0, hb1, hb2, hb3 };
#pragma unroll
        for (int q = 0; q < 8; q++) {            // d = 4q .. 4q+3
            u64 bb0, bb1;
            lds_v2b64(sbase + (OFF_B1 + 4 * q) * 4, bb0, bb1);
            u64 w00, w01, w10, w11, w20, w21;
            lds_v2b64(sbase + (OFF_W1 + 0 * 32 + 4 * q) * 4, w00, w01);
            lds_v2b64(sbase + (OFF_W1 + 1 * 32 + 4 * q) * 4, w10, w11);
            lds_v2b64(sbase + (OFF_W1 + 2 * 32 + 4 * q) * 4, w20, w21);
#pragma unroll
            for (int p = 0; p < NP; p++) {
                u64 a0 = bb0, a1 = bb1;
                a0 = ffma2(cd[p][0], w00, a0);
                a1 = ffma2(cd[p][0], w01, a1);
                a0 = ffma2(cd[p][1], w10, a0);
                a1 = ffma2(cd[p][1], w11, a1);
                a0 = ffma2(cd[p][2], w20, a0);
                a1 = ffma2(cd[p][2], w21, a1);
                float l0, h0f, l1, h1f;
                upk2(a0, l0, h0f); upk2(a1, l1, h1f);
                sts_f32(hb[p] + (4 * q + 0) * 128, __cosf(l0));
                sts_f32(hb[p] + (4 * q + 1) * 128, __cosf(h0f));
                sts_f32(hb[p] + (4 * q + 2) * 128, __cosf(l1));
                sts_f32(hb[p] + (4 * q + 3) * 128, __cosf(h1f));
            }
        }
    }

    // ---- Layers 2 and 3 ----
    dense_cos_layer(sbase, OFF_W2, OFF_B2, hb0, hb1, hb2, hb3);
    dense_cos_layer(sbase, OFF_W3, OFF_B3, hb0, hb1, hb2, hb3);

    // ---- Final: coord = c + 5 * (h @ Wf + bf)  (Wf padded to [32][4]) ----
    float pco[NP][3];
    {
        u64 bf01 = lds_b64(sbase + OFF_BF * 4);
        u64 bf2x = lds_b64(sbase + (OFF_BF + 2) * 4);
        u64 e01[NP], e2[NP];
#pragma unroll
        for (int p = 0; p < NP; p++) { e01[p] = bf01; e2[p] = bf2x; }
#pragma unroll 8
        for (int k = 0; k < 32; k++) {
            u64 w01, w2x;
            lds_v2b64(sbase + (OFF_WF4 + 4 * k) * 4, w01, w2x);
            u64 h0 = dup2(lds_f32(hb0 + k * 128));
            u64 h1 = dup2(lds_f32(hb1 + k * 128));
            u64 h2 = dup2(lds_f32(hb2 + k * 128));
            u64 h3 = dup2(lds_f32(hb3 + k * 128));
            e01[0] = ffma2(h0, w01, e01[0]);  e2[0] = ffma2(h0, w2x, e2[0]);
            e01[1] = ffma2(h1, w01, e01[1]);  e2[1] = ffma2(h1, w2x, e2[1]);
            e01[2] = ffma2(h2, w01, e01[2]);  e2[2] = ffma2(h2, w2x, e2[2]);
            e01[3] = ffma2(h3, w01, e01[3]);  e2[3] = ffma2(h3, w2x, e2[3]);
        }
#pragma unroll
        for (int p = 0; p < NP; p++) {
            float f0, f1, f2, jk;
            upk2(e01[p], f0, f1);
            upk2(e2[p], f2, jk);
            pco[p][0] = fmaf(5.0f, f0, cxr[p][0]);
            pco[p][1] = fmaf(5.0f, f1, cxr[p][1]);
            pco[p][2] = fmaf(5.0f, f2, cxr[p][2]);
        }
    }

    // ---- Trilinear sample (scalar per point) ----
    float res[NP];
#pragma unroll
    for (int p = 0; p < NP; p++) {
        float cx = fminf(fmaxf(pco[p][0], 0.0f), 255.0f);
        float cy = fminf(fmaxf(pco[p][1], 0.0f), 255.0f);
        float cz = fminf(fmaxf(pco[p][2], 0.0f), 255.0f);

        float fx0 = floorf(cx), fy0 = floorf(cy), fz0 = floorf(cz);
        int ix0 = (int)fx0, iy0 = (int)fy0, iz0 = (int)fz0;
        int ix1 = min(ix0 + 1, 255);
        int iy1 = min(iy0 + 1, 255);
        int iz1 = min(iz0 + 1, 255);

        float fx = cx - fx0, fy = cy - fy0, fz = cz - fz0;
        float gx = 1.0f - fx, gy = 1.0f - fy, gz = 1.0f - fz;

        int Xa = ix0 << 16, Xb = ix1 << 16;
        int Ya = iy0 << 8,  Yb = iy1 << 8;

        float v000 = __ldg(vol + (Xa + Ya + iz0));
        float v100 = __ldg(vol + (Xb + Ya + iz0));
        float v010 = __ldg(vol + (Xa + Yb + iz0));
        float v001 = __ldg(vol + (Xa + Ya + iz1));
        float v110 = __ldg(vol + (Xb + Yb + iz0));
        float v101 = __ldg(vol + (Xb + Ya + iz1));
        float v011 = __ldg(vol + (Xa + Yb + iz1));
        float v111 = __ldg(vol + (Xb + Yb + iz1));

        float r;
        r  = v000 * (gx * gy * gz);
        r += v100 * (fx * gy * gz);
        r += v010 * (gx * fy * gz);
        r += v001 * (gx * gy * fz);
        r += v110 * (fx * fy * gz);
        r += v101 * (fx * gy * fz);
        r += v011 * (gx * fy * fz);
        r += v111 * (fx * fy * fz);
        res[p] = r;
    }

    float4 o; o.x = res[0]; o.y = res[1]; o.z = res[2]; o.w = res[3];
    reinterpret_cast<float4*>(out)[t] = o;
}

extern "C" void kernel_launch(void* const* d_in, const int* in_sizes, int n_in,
                              void* d_out, int out_size) {
    const float* x   = (const float*)d_in[0];
    const float* W1  = (const float*)d_in[1];
    const float* b1  = (const float*)d_in[2];
    const float* W2  = (const float*)d_in[3];
    const float* b2  = (const float*)d_in[4];
    const float* W3  = (const float*)d_in[5];
    const float* b3  = (const float*)d_in[6];
    const float* Wf  = (const float*)d_in[7];
    const float* bf  = (const float*)d_in[8];
    const float* vol = (const float*)d_in[9];
    float* out = (float*)d_out;

    cudaFuncSetAttribute(deform_sample_kernel,
                         cudaFuncAttributeMaxDynamicSharedMemorySize, SMEM_BYTES);

    int npts = out_size;                 // 2,097,152 points
    int nthreads = npts / NP;            // 4 points per thread
    int grid = (nthreads + BLK - 1) / BLK;

    deform_sample_kernel<<<grid, BLK, SMEM_BYTES>>>(
        x, W1, b1, W2, b2, W3, b3, Wf, bf, vol, out, nthreads);
}

// round 8
// speedup vs baseline: 2.0859x; 2.0859x over previous
#include <cuda_runtime.h>

// ---------------------------------------------------------------------------
// RModel_29257317221019: fused cos-MLP deform (3->32->32->32->3) + trilinear
// sample from 256^3 volume.
// R6 structure (2 points/thread, f32x2 over output pairs) but ALL weights in
// __constant__ memory: weight fetches use the constant port (uniform LDCU),
// freeing the L1/shared pipe for the trilinear gather.
// Weights arrive via cudaMemcpyToSymbolAsync D2D (capturable memcpy node).
// ---------------------------------------------------------------------------

typedef unsigned long long u64;

__device__ __forceinline__ void upk2(u64 v, float& lo, float& hi) {
    asm("mov.b64 {%0, %1}, %2;" : "=f"(lo), "=f"(hi) : "l"(v));
}
__device__ __forceinline__ u64 dup2(float v) {
    u64 r; asm("mov.b64 %0, {%1, %1};" : "=l"(r) : "f"(v)); return r;
}
__device__ __forceinline__ u64 ffma2(u64 a, u64 b, u64 c) {
    u64 r; asm("fma.rn.f32x2 %0, %1, %2, %3;" : "=l"(r) : "l"(a), "l"(b), "l"(c)); return r;
}

// Weights in constant memory, typed u64 so each load is an f32x2 operand pair.
// Layouts are the raw row-major float layouts reinterpreted:
//   cW1[c][j]  = (W1[c*32+2j], W1[c*32+2j+1])
//   cW2[k][j]  = (W2[k*32+2j], W2[k*32+2j+1]), same for cW3
__constant__ u64   cW1[3][16];
__constant__ u64   cB1[16];
__constant__ u64   cW2[32][16];
__constant__ u64   cB2[16];
__constant__ u64   cW3[32][16];
__constant__ u64   cB3[16];
__constant__ float cWf[96];     // raw [32][3] (k*3+j)
__constant__ float cBf[3];

#define BLK 128

__global__ __launch_bounds__(BLK, 3)
void deform_sample_kernel(
    const float* __restrict__ x,
    const float* __restrict__ vol,
    float* __restrict__ out,
    int npairs)
{
    int t = blockIdx.x * blockDim.x + threadIdx.x;
    if (t >= npairs) return;

    // Two consecutive points (x layout: 4 floats/point, coords in [0:3])
    const float4* x4 = reinterpret_cast<const float4*>(x);
    float4 XA = x4[2 * t + 0];
    float4 XB = x4[2 * t + 1];

    float hA[32], hB[32];
    u64 aA[16], aB[16];

    // ---- Layer 1: h = cos(c @ W1 + b1) ----
    {
        u64 cA0 = dup2(XA.x), cA1 = dup2(XA.y), cA2 = dup2(XA.z);
        u64 cB0 = dup2(XB.x), cB1v = dup2(XB.y), cB2v = dup2(XB.z);
#pragma unroll
        for (int q = 0; q < 8; q++) {           // d = 4q .. 4q+3  (j = 2q, 2q+1)
            u64 b0 = cB1[2 * q], b1p = cB1[2 * q + 1];
            u64 pA0 = b0, pA1 = b1p, pB0 = b0, pB1 = b1p;
#pragma unroll
            for (int c = 0; c < 3; c++) {
                u64 w0 = cW1[c][2 * q];
                u64 w1p = cW1[c][2 * q + 1];
                u64 ca = (c == 0) ? cA0 : (c == 1) ? cA1 : cA2;
                u64 cb = (c == 0) ? cB0 : (c == 1) ? cB1v : cB2v;
                pA0 = ffma2(ca, w0, pA0);
                pA1 = ffma2(ca, w1p, pA1);
                pB0 = ffma2(cb, w0, pB0);
                pB1 = ffma2(cb, w1p, pB1);
            }
            float lo, hi;
            upk2(pA0, lo, hi); hA[4*q]   = __cosf(lo); hA[4*q+1] = __cosf(hi);
            upk2(pA1, lo, hi); hA[4*q+2] = __cosf(lo); hA[4*q+3] = __cosf(hi);
            upk2(pB0, lo, hi); hB[4*q]   = __cosf(lo); hB[4*q+1] = __cosf(hi);
            upk2(pB1, lo, hi); hB[4*q+2] = __cosf(lo); hB[4*q+3] = __cosf(hi);
        }
    }

    // ---- Layer 2: h = cos(h @ W2 + b2) ----
#pragma unroll
    for (int j = 0; j < 16; j++) { u64 b = cB2[j]; aA[j] = b; aB[j] = b; }
#pragma unroll
    for (int k = 0; k < 32; k++) {
        u64 dA = dup2(hA[k]);
        u64 dB = dup2(hB[k]);
#pragma unroll
        for (int j = 0; j < 16; j++) {
            u64 w = cW2[k][j];
            aA[j] = ffma2(dA, w, aA[j]);
            aB[j] = ffma2(dB, w, aB[j]);
        }
    }
#pragma unroll
    for (int p = 0; p < 16; p++) {
        float lo, hi;
        upk2(aA[p], lo, hi); hA[2*p] = __cosf(lo); hA[2*p+1] = __cosf(hi);
        upk2(aB[p], lo, hi); hB[2*p] = __cosf(lo); hB[2*p+1] = __cosf(hi);
    }

    // ---- Layer 3: h = cos(h @ W3 + b3) ----
#pragma unroll
    for (int j = 0; j < 16; j++) { u64 b = cB3[j]; aA[j] = b; aB[j] = b; }
#pragma unroll
    for (int k = 0; k < 32; k++) {
        u64 dA = dup2(hA[k]);
        u64 dB = dup2(hB[k]);
#pragma unroll
        for (int j = 0; j < 16; j++) {
            u64 w = cW3[k][j];
            aA[j] = ffma2(dA, w, aA[j]);
            aB[j] = ffma2(dB, w, aB[j]);
        }
    }
#pragma unroll
    for (int p = 0; p < 16; p++) {
        float lo, hi;
        upk2(aA[p], lo, hi); hA[2*p] = __cosf(lo); hA[2*p+1] = __cosf(hi);
        upk2(aB[p], lo, hi); hB[2*p] = __cosf(lo); hB[2*p+1] = __cosf(hi);
    }

    // ---- Final: coord = c + 5 * (h @ Wf + bf), scalar (Wf raw [32][3]) ----
    float pxy[2][3];
    {
        float eA0 = cBf[0], eA1 = cBf[1], eA2 = cBf[2];
        float eB0 = cBf[0], eB1 = cBf[1], eB2 = cBf[2];
#pragma unroll
        for (int k = 0; k < 32; k++) {
            float w0 = cWf[k * 3 + 0];
            float w1 = cWf[k * 3 + 1];
            float w2 = cWf[k * 3 + 2];
            eA0 = fmaf(hA[k], w0, eA0);
            eA1 = fmaf(hA[k], w1, eA1);
            eA2 = fmaf(hA[k], w2, eA2);
            eB0 = fmaf(hB[k], w0, eB0);
            eB1 = fmaf(hB[k], w1, eB1);
            eB2 = fmaf(hB[k], w2, eB2);
        }
        pxy[0][0] = fmaf(5.0f, eA0, XA.x);
        pxy[0][1] = fmaf(5.0f, eA1, XA.y);
        pxy[0][2] = fmaf(5.0f, eA2, XA.z);
        pxy[1][0] = fmaf(5.0f, eB0, XB.x);
        pxy[1][1] = fmaf(5.0f, eB1, XB.y);
        pxy[1][2] = fmaf(5.0f, eB2, XB.z);
    }

    // ---- Trilinear sample (scalar per point) ----
    float res[2];
#pragma unroll
    for (int s = 0; s < 2; s++) {
        float cx = fminf(fmaxf(pxy[s][0], 0.0f), 255.0f);
        float cy = fminf(fmaxf(pxy[s][1], 0.0f), 255.0f);
        float cz = fminf(fmaxf(pxy[s][2], 0.0f), 255.0f);

        float fx0 = floorf(cx), fy0 = floorf(cy), fz0 = floorf(cz);
        int ix0 = (int)fx0, iy0 = (int)fy0, iz0 = (int)fz0;
        int ix1 = min(ix0 + 1, 255);
        int iy1 = min(iy0 + 1, 255);
        int iz1 = min(iz0 + 1, 255);

        float fx = cx - fx0, fy = cy - fy0, fz = cz - fz0;
        float gx = 1.0f - fx, gy = 1.0f - fy, gz = 1.0f - fz;

        int X0 = ix0 << 16, X1 = ix1 << 16;
        int Y0 = iy0 << 8,  Y1 = iy1 << 8;

        float v000 = __ldg(vol + (X0 + Y0 + iz0));
        float v100 = __ldg(vol + (X1 + Y0 + iz0));
        float v010 = __ldg(vol + (X0 + Y1 + iz0));
        float v001 = __ldg(vol + (X0 + Y0 + iz1));
        float v110 = __ldg(vol + (X1 + Y1 + iz0));
        float v101 = __ldg(vol + (X1 + Y0 + iz1));
        float v011 = __ldg(vol + (X0 + Y1 + iz1));
        float v111 = __ldg(vol + (X1 + Y1 + iz1));

        float r;
        r  = v000 * (gx * gy * gz);
        r += v100 * (fx * gy * gz);
        r += v010 * (gx * fy * gz);
        r += v001 * (gx * gy * fz);
        r += v110 * (fx * fy * gz);
        r += v101 * (fx * gy * fz);
        r += v011 * (gx * fy * fz);
        r += v111 * (fx * fy * fz);
        res[s] = r;
    }

    float2 o; o.x = res[0]; o.y = res[1];
    reinterpret_cast<float2*>(out)[t] = o;
}

extern "C" void kernel_launch(void* const* d_in, const int* in_sizes, int n_in,
                              void* d_out, int out_size) {
    const float* x   = (const float*)d_in[0];
    const float* vol = (const float*)d_in[9];
    float* out = (float*)d_out;

    // Stage weights into constant memory (D2D memcpy nodes; graph-capturable,
    // no allocation). Byte layouts of the u64 symbols match the raw floats.
    cudaMemcpyToSymbolAsync(cW1, d_in[1], 3  * 32 * 4, 0, cudaMemcpyDeviceToDevice, 0);
    cudaMemcpyToSymbolAsync(cB1, d_in[2], 32 * 4,      0, cudaMemcpyDeviceToDevice, 0);
    cudaMemcpyToSymbolAsync(cW2, d_in[3], 32 * 32 * 4, 0, cudaMemcpyDeviceToDevice, 0);
    cudaMemcpyToSymbolAsync(cB2, d_in[4], 32 * 4,      0, cudaMemcpyDeviceToDevice, 0);
    cudaMemcpyToSymbolAsync(cW3, d_in[5], 32 * 32 * 4, 0, cudaMemcpyDeviceToDevice, 0);
    cudaMemcpyToSymbolAsync(cB3, d_in[6], 32 * 4,      0, cudaMemcpyDeviceToDevice, 0);
    cudaMemcpyToSymbolAsync(cWf, d_in[7], 32 * 3 * 4,  0, cudaMemcpyDeviceToDevice, 0);
    cudaMemcpyToSymbolAsync(cBf, d_in[8], 3 * 4,       0, cudaMemcpyDeviceToDevice, 0);

    int npts = out_size;           // 2,097,152 points
    int npairs = npts / 2;         // 2 points per thread
    int grid = (npairs + BLK - 1) / BLK;

    deform_sample_kernel<<<grid, BLK>>>(x, vol, out, npairs);
}

// round 9
// speedup vs baseline: 2.1283x; 1.0204x over previous
#include <cuda_runtime.h>

// ---------------------------------------------------------------------------
// RModel_29257317221019: fused cos-MLP deform (3->32->32->32->3) + trilinear
// sample from 256^3 volume.
// 2 points/thread, f32x2 over output pairs, ALL weights in __constant__
// (uniform constant-port loads). This round:
//   - __launch_bounds__(128,4): 16 warps/SM (cap 128 regs, minor cold spills)
//   - final layer re-packed as f32x2 via prep kernel -> padded Wf pairs in
//     constant memory (saves ~190 fma-cycles/thread)
// ---------------------------------------------------------------------------

typedef unsigned long long u64;

__device__ __forceinline__ void upk2(u64 v, float& lo, float& hi) {
    asm("mov.b64 {%0, %1}, %2;" : "=f"(lo), "=f"(hi) : "l"(v));
}
__device__ __forceinline__ u64 pk2(float lo, float hi) {
    u64 r; asm("mov.b64 %0, {%1, %2};" : "=l"(r) : "f"(lo), "f"(hi)); return r;
}
__device__ __forceinline__ u64 dup2(float v) {
    u64 r; asm("mov.b64 %0, {%1, %1};" : "=l"(r) : "f"(v)); return r;
}
__device__ __forceinline__ u64 ffma2(u64 a, u64 b, u64 c) {
    u64 r; asm("fma.rn.f32x2 %0, %1, %2, %3;" : "=l"(r) : "l"(a), "l"(b), "l"(c)); return r;
}

// Weights in constant memory (u64 = f32x2 operand pairs, raw layouts):
__constant__ u64 cW1[3][16];
__constant__ u64 cB1[16];
__constant__ u64 cW2[32][16];
__constant__ u64 cB2[16];
__constant__ u64 cW3[32][16];
__constant__ u64 cB3[16];
// Final layer, prepacked by prep_kernel:
//   cWfP[2k]   = (Wf[k][0], Wf[k][1]),  cWfP[2k+1] = (Wf[k][2], 0)
//   cWfP[64]   = (bf0, bf1),            cWfP[65]   = (bf2, 0)
__constant__ u64 cWfP[66];

__device__ u64 g_wf_scratch[66];

__global__ void prep_kernel(const float* __restrict__ Wf,
                            const float* __restrict__ bf) {
    int k = threadIdx.x;
    if (k < 32) {
        g_wf_scratch[2 * k]     = pk2(Wf[3 * k + 0], Wf[3 * k + 1]);
        g_wf_scratch[2 * k + 1] = pk2(Wf[3 * k + 2], 0.0f);
    }
    if (k == 0) {
        g_wf_scratch[64] = pk2(bf[0], bf[1]);
        g_wf_scratch[65] = pk2(bf[2], 0.0f);
    }
}

#define BLK 128

__global__ __launch_bounds__(BLK, 4)
void deform_sample_kernel(
    const float* __restrict__ x,
    const float* __restrict__ vol,
    float* __restrict__ out,
    int npairs)
{
    int t = blockIdx.x * blockDim.x + threadIdx.x;
    if (t >= npairs) return;

    // Two consecutive points (x layout: 4 floats/point, coords in [0:3])
    const float4* x4 = reinterpret_cast<const float4*>(x);
    float4 XA = x4[2 * t + 0];
    float4 XB = x4[2 * t + 1];

    float hA[32], hB[32];
    u64 aA[16], aB[16];

    // ---- Layer 1: h = cos(c @ W1 + b1) ----
    {
        u64 cA0 = dup2(XA.x), cA1 = dup2(XA.y), cA2 = dup2(XA.z);
        u64 cB0 = dup2(XB.x), cB1v = dup2(XB.y), cB2v = dup2(XB.z);
#pragma unroll
        for (int q = 0; q < 8; q++) {           // d = 4q .. 4q+3  (j = 2q, 2q+1)
            u64 b0 = cB1[2 * q], b1p = cB1[2 * q + 1];
            u64 pA0 = b0, pA1 = b1p, pB0 = b0, pB1 = b1p;
#pragma unroll
            for (int c = 0; c < 3; c++) {
                u64 w0 = cW1[c][2 * q];
                u64 w1p = cW1[c][2 * q + 1];
                u64 ca = (c == 0) ? cA0 : (c == 1) ? cA1 : cA2;
                u64 cb = (c == 0) ? cB0 : (c == 1) ? cB1v : cB2v;
                pA0 = ffma2(ca, w0, pA0);
                pA1 = ffma2(ca, w1p, pA1);
                pB0 = ffma2(cb, w0, pB0);
                pB1 = ffma2(cb, w1p, pB1);
            }
            float lo, hi;
            upk2(pA0, lo, hi); hA[4*q]   = __cosf(lo); hA[4*q+1] = __cosf(hi);
            upk2(pA1, lo, hi); hA[4*q+2] = __cosf(lo); hA[4*q+3] = __cosf(hi);
            upk2(pB0, lo, hi); hB[4*q]   = __cosf(lo); hB[4*q+1] = __cosf(hi);
            upk2(pB1, lo, hi); hB[4*q+2] = __cosf(lo); hB[4*q+3] = __cosf(hi);
        }
    }

    // ---- Layer 2: h = cos(h @ W2 + b2) ----
#pragma unroll
    for (int j = 0; j < 16; j++) { u64 b = cB2[j]; aA[j] = b; aB[j] = b; }
#pragma unroll
    for (int k = 0; k < 32; k++) {
        u64 dA = dup2(hA[k]);
        u64 dB = dup2(hB[k]);
#pragma unroll
        for (int j = 0; j < 16; j++) {
            u64 w = cW2[k][j];
            aA[j] = ffma2(dA, w, aA[j]);
            aB[j] = ffma2(dB, w, aB[j]);
        }
    }
#pragma unroll
    for (int p = 0; p < 16; p++) {
        float lo, hi;
        upk2(aA[p], lo, hi); hA[2*p] = __cosf(lo); hA[2*p+1] = __cosf(hi);
        upk2(aB[p], lo, hi); hB[2*p] = __cosf(lo); hB[2*p+1] = __cosf(hi);
    }

    // ---- Layer 3: h = cos(h @ W3 + b3) ----
#pragma unroll
    for (int j = 0; j < 16; j++) { u64 b = cB3[j]; aA[j] = b; aB[j] = b; }
#pragma unroll
    for (int k = 0; k < 32; k++) {
        u64 dA = dup2(hA[k]);
        u64 dB = dup2(hB[k]);
#pragma unroll
        for (int j = 0; j < 16; j++) {
            u64 w = cW3[k][j];
            aA[j] = ffma2(dA, w, aA[j]);
            aB[j] = ffma2(dB, w, aB[j]);
        }
    }
#pragma unroll
    for (int p = 0; p < 16; p++) {
        float lo, hi;
        upk2(aA[p], lo, hi); hA[2*p] = __cosf(lo); hA[2*p+1] = __cosf(hi);
        upk2(aB[p], lo, hi); hB[2*p] = __cosf(lo); hB[2*p+1] = __cosf(hi);
    }

    // ---- Final: coord = c + 5 * (h @ Wf + bf), packed pairs ----
    float pxy[2][3];
    {
        u64 eA01 = cWfP[64], eA2 = cWfP[65];
        u64 eB01 = eA01,     eB2 = eA2;
#pragma unroll
        for (int k = 0; k < 32; k++) {
            u64 w01 = cWfP[2 * k];
            u64 w2x = cWfP[2 * k + 1];
            u64 dA = dup2(hA[k]);
            u64 dB = dup2(hB[k]);
            eA01 = ffma2(dA, w01, eA01);
            eA2  = ffma2(dA, w2x, eA2);
            eB01 = ffma2(dB, w01, eB01);
            eB2  = ffma2(dB, w2x, eB2);
        }
        float f0, f1, f2, jk;
        upk2(eA01, f0, f1); upk2(eA2, f2, jk);
        pxy[0][0] = fmaf(5.0f, f0, XA.x);
        pxy[0][1] = fmaf(5.0f, f1, XA.y);
        pxy[0][2] = fmaf(5.0f, f2, XA.z);
        upk2(eB01, f0, f1); upk2(eB2, f2, jk);
        pxy[1][0] = fmaf(5.0f, f0, XB.x);
        pxy[1][1] = fmaf(5.0f, f1, XB.y);
        pxy[1][2] = fmaf(5.0f, f2, XB.z);
    }

    // ---- Trilinear sample (scalar per point) ----
    float res[2];
#pragma unroll
    for (int s = 0; s < 2; s++) {
        float cx = fminf(fmaxf(pxy[s][0], 0.0f), 255.0f);
        float cy = fminf(fmaxf(pxy[s][1], 0.0f), 255.0f);
        float cz = fminf(fmaxf(pxy[s][2], 0.0f), 255.0f);

        float fx0 = floorf(cx), fy0 = floorf(cy), fz0 = floorf(cz);
        int ix0 = (int)fx0, iy0 = (int)fy0, iz0 = (int)fz0;
        int ix1 = min(ix0 + 1, 255);
        int iy1 = min(iy0 + 1, 255);
        int iz1 = min(iz0 + 1, 255);

        float fx = cx - fx0, fy = cy - fy0, fz = cz - fz0;
        float gx = 1.0f - fx, gy = 1.0f - fy, gz = 1.0f - fz;

        int X0 = ix0 << 16, X1 = ix1 << 16;
        int Y0 = iy0 << 8,  Y1 = iy1 << 8;

        float v000 = __ldg(vol + (X0 + Y0 + iz0));
        float v100 = __ldg(vol + (X1 + Y0 + iz0));
        float v010 = __ldg(vol + (X0 + Y1 + iz0));
        float v001 = __ldg(vol + (X0 + Y0 + iz1));
        float v110 = __ldg(vol + (X1 + Y1 + iz0));
        float v101 = __ldg(vol + (X1 + Y0 + iz1));
        float v011 = __ldg(vol + (X0 + Y1 + iz1));
        float v111 = __ldg(vol + (X1 + Y1 + iz1));

        float r;
        r  = v000 * (gx * gy * gz);
        r += v100 * (fx * gy * gz);
        r += v010 * (gx * fy * gz);
        r += v001 * (gx * gy * fz);
        r += v110 * (fx * fy * gz);
        r += v101 * (fx * gy * fz);
        r += v011 * (gx * fy * fz);
        r += v111 * (fx * fy * fz);
        res[s] = r;
    }

    float2 o; o.x = res[0]; o.y = res[1];
    reinterpret_cast<float2*>(out)[t] = o;
}

extern "C" void kernel_launch(void* const* d_in, const int* in_sizes, int n_in,
                              void* d_out, int out_size) {
    const float* x   = (const float*)d_in[0];
    const float* vol = (const float*)d_in[9];
    float* out = (float*)d_out;

    // Stage weights into constant memory (D2D memcpy nodes; capturable).
    cudaMemcpyToSymbolAsync(cW1, d_in[1], 3  * 32 * 4, 0, cudaMemcpyDeviceToDevice, 0);
    cudaMemcpyToSymbolAsync(cB1, d_in[2], 32 * 4,      0, cudaMemcpyDeviceToDevice, 0);
    cudaMemcpyToSymbolAsync(cW2, d_in[3], 32 * 32 * 4, 0, cudaMemcpyDeviceToDevice, 0);
    cudaMemcpyToSymbolAsync(cB2, d_in[4], 32 * 4,      0, cudaMemcpyDeviceToDevice, 0);
    cudaMemcpyToSymbolAsync(cW3, d_in[5], 32 * 32 * 4, 0, cudaMemcpyDeviceToDevice, 0);
    cudaMemcpyToSymbolAsync(cB3, d_in[6], 32 * 4,      0, cudaMemcpyDeviceToDevice, 0);

    // Prepack final-layer pairs on device, then stage into constant memory.
    prep_kernel<<<1, 32>>>((const float*)d_in[7], (const float*)d_in[8]);
    void* scratch_ptr = 0;
    cudaGetSymbolAddress(&scratch_ptr, g_wf_scratch);
    cudaMemcpyToSymbolAsync(cWfP, scratch_ptr, 66 * 8, 0, cudaMemcpyDeviceToDevice, 0);

    int npts = out_size;           // 2,097,152 points
    int npairs = npts / 2;         // 2 points per thread
    int grid = (npairs + BLK - 1) / BLK;

    deform_sample_kernel<<<grid, BLK>>>(x, vol, out, npairs);
}